// round 9
// baseline (speedup 1.0000x reference)
#include <cuda_runtime.h>

#define SS 512
#define BB 64
#define HH 8
#define KK 12
#define TT 4096
#define THRESH 4

// partial parities: [half][h][s][b] — fully overwritten each call
__device__ unsigned char g_par[2 * HH * SS * BB];
__device__ unsigned int  g_tokbits[SS * 2];     // fully overwritten each call
__device__ unsigned int  g_ctr;                 // zero-init; returns to 0 each call

// ---- kernel 1: bit-pack tokens (S,B) -> 4KB ----
__global__ void __launch_bounds__(128) softram_packtok_kernel(const int* __restrict__ tokens)
{
    const int gwarp = (blockIdx.x * 128 + threadIdx.x) >> 5;   // 0..63
    const int lane  = threadIdx.x & 31;
    #pragma unroll
    for (int m = 0; m < 8; ++m) {
        const int s = gwarp * 8 + m;
        const unsigned lo = __ballot_sync(0xffffffffu, tokens[s * BB + lane] & 1);
        const unsigned hi = __ballot_sync(0xffffffffu, tokens[s * BB + 32 + lane] & 1);
        if (lane == 0) {
            g_tokbits[2 * s]     = lo;
            g_tokbits[2 * s + 1] = hi;
        }
    }
}

// ---- kernel 2: main triangular XOR-gather + fused last-CTA vote ----
__global__ void __launch_bounds__(128, 8) softram_main_kernel(
    const int* __restrict__ conn,     // (H, B, K)
    const float* __restrict__ ram,    // (H, B, T)
    float* __restrict__ out)          // (S*B), idx = s*B+b
{
    const int bid  = blockIdx.x;
    const int hb   = bid >> 1;
    const int half = bid & 1;
    const int h    = hb >> 6;
    const int b    = hb & (BB - 1);
    const int tid  = threadIdx.x;
    const int lane = tid & 31;

    __shared__ int      sc[KK];
    __shared__ unsigned stok[SS * 2];        // 4KB packed tokens
    __shared__ unsigned sAqq[SS];            // aq_i * 0x10001
    __shared__ unsigned sAkP[SS / 2];        // word p: lo=ak_{2p+1}, hi=ak_{2p}
    __shared__ unsigned sArP[SS / 2 + 1];    // word q: lo=ar_{2q}, hi=ar_{2q+1}
    __shared__ unsigned tbl[(TT / 32) * 32]; // per-lane replicated bit table (16KB)

    if (tid < KK) sc[tid] = conn[hb * KK + tid];
    for (int i = tid; i < SS * 2; i += 128) stok[i] = g_tokbits[i];
    __syncthreads();

    // ---- address components (pure ALU from packed token bits) ----
    for (int s = tid; s < SS; s += 128) {
        unsigned aq = 0, ak = 0, ar = 0;
        #pragma unroll
        for (int k = 0; k < KK; ++k) {
            const int c = sc[k];                       // warp-uniform
            if (c < BB) {
                aq |= ((stok[2 * s + (c >> 5)] >> (c & 31)) & 1u) << k;
            } else if (c < 2 * BB) {
                const int cc = c - BB;
                ak |= ((stok[2 * s + (cc >> 5)] >> (cc & 31)) & 1u) << k;
            } else {
                ar |= (unsigned)((s >> (c - 2 * BB)) & 1) << k;
            }
        }
        sAqq[s] = aq * 0x10001u;
        ((unsigned short*)sAkP)[s ^ 1] = (unsigned short)ak;
        ((unsigned short*)sArP)[s]     = (unsigned short)ar;
    }

    // ---- pack RAM bits into per-lane replicated table (bank = lane) ----
    {
        const float* rp = ram + (size_t)hb * TT;
        for (int t = tid; t < TT; t += 128) {
            const unsigned wv = __ballot_sync(0xffffffffu, rp[t] > 0.5f);
            tbl[(t & 0xFE0) + lane] = wv;              // word (t>>5) at its lane column
        }
    }
    __syncthreads();

    const unsigned* tl = tbl + lane;                   // lane-private bank column
    unsigned char* gp  = g_par + ((size_t)(half * HH + h) * SS) * BB + b;

    // process quad m: rows ia=2m (accA), ib=2m+1 (accB); pairs p in [p0,p1), optional tail
    #pragma unroll
    for (int q = 0; q < 2; ++q) {
        const int m  = q ? (255 - tid) : tid;
        const int h0 = (m + 1) >> 1;
        const int p0 = half ? h0 : 0;
        const int p1 = half ? m  : h0;

        const unsigned aqA = sAqq[2 * m];
        const unsigned aqB = sAqq[2 * m + 1];
        unsigned accA = 0, accB = 0;

        // B_p (row ib, direct): sArP[m-p] = (ar_{2m-2p+1}<<16)|ar_{2m-2p}
        // A_p (row ia) = prmt(B_{p+1}, B_p, 0x5432) = (ar_{2m-2p}<<16)|ar_{2m-2p-1}
        unsigned Bcur = sArP[m - p0];
        #pragma unroll 4
        for (int p = p0; p < p1; ++p) {
            const unsigned pka   = sAkP[p];
            const unsigned Bnext = sArP[m - p - 1];
            const unsigned Ap    = __byte_perm(Bnext, Bcur, 0x5432);
            const unsigned pxA   = pka ^ Ap   ^ aqA;   // lo:(ia,2p+1) hi:(ia,2p)
            const unsigned pxB   = pka ^ Bcur ^ aqB;   // lo:(ib,2p+1) hi:(ib,2p)
            const unsigned xA1   = pxA >> 16;
            const unsigned xB1   = pxB >> 16;
            const unsigned wA0 = tl[pxA & 0xFE0u];
            const unsigned wA1 = tl[xA1 & 0xFE0u];
            const unsigned wB0 = tl[pxB & 0xFE0u];
            const unsigned wB1 = tl[xB1 & 0xFE0u];
            accA ^= __funnelshift_r(wA0, wA0, pxA);    // target bit lands at bit 0
            accA ^= __funnelshift_r(wA1, wA1, xA1);
            accB ^= __funnelshift_r(wB0, wB0, pxB);
            accB ^= __funnelshift_r(wB1, wB1, xB1);
            Bcur = Bnext;
        }

        if (half) {   // tail: (ia, j=2m) ; (ib, j=2m) ; (ib, j=2m+1)
            const unsigned ak2  = sAkP[m];             // lo=ak_{2m+1}, hi=ak_{2m}
            const unsigned ar01 = sArP[0];             // lo=ar_0, hi=ar_1
            const unsigned xa   = (aqA & 0xFFFFu) ^ (ak2 >> 16) ^ (ar01 & 0xFFFFu);
            const unsigned wa   = tl[xa & 0xFE0u];
            accA ^= __funnelshift_r(wa, wa, xa);
            const unsigned pxT  = ak2 ^ ar01 ^ aqB;    // lo:(ib,2m+1,ar_0) hi:(ib,2m,ar_1)
            const unsigned xT1  = pxT >> 16;
            const unsigned wt0  = tl[pxT & 0xFE0u];
            const unsigned wt1  = tl[xT1 & 0xFE0u];
            accB ^= __funnelshift_r(wt0, wt0, pxT);
            accB ^= __funnelshift_r(wt1, wt1, xT1);
        }

        // every contribution deposits its bit at bit 0 -> parity is acc & 1
        gp[(size_t)(2 * m)     * BB] = (unsigned char)(accA & 1u);
        gp[(size_t)(2 * m + 1) * BB] = (unsigned char)(accB & 1u);
    }

    // ---- fused reduce: last CTA XORs the two half-slabs, votes, thresholds ----
    __threadfence();
    __shared__ int slast;
    __syncthreads();
    if (tid == 0) slast = (atomicAdd(&g_ctr, 1u) == (unsigned)(gridDim.x - 1)) ? 1 : 0;
    __syncthreads();
    if (slast) {
        __threadfence();
        const unsigned* pw = (const unsigned*)g_par;
        for (int g = tid; g < SS * BB / 4; g += 128) {
            unsigned sum4 = 0;
            #pragma unroll
            for (int hh = 0; hh < HH; ++hh)
                sum4 += pw[hh * (SS * BB / 4) + g] ^ pw[(HH + hh) * (SS * BB / 4) + g];
            float4 o;
            o.x = (( sum4        & 0xffu) > THRESH) ? 1.0f : 0.0f;
            o.y = (((sum4 >> 8)  & 0xffu) > THRESH) ? 1.0f : 0.0f;
            o.z = (((sum4 >> 16) & 0xffu) > THRESH) ? 1.0f : 0.0f;
            o.w = (((sum4 >> 24) & 0xffu) > THRESH) ? 1.0f : 0.0f;
            ((float4*)out)[g] = o;
        }
        if (tid == 0) g_ctr = 0;   // reset for next graph replay
    }
}

extern "C" void kernel_launch(void* const* d_in, const int* in_sizes, int n_in,
                              void* d_out, int out_size)
{
    const int*   tokens = (const int*)d_in[0];
    const int*   conn   = (const int*)d_in[1];
    const float* ram    = (const float*)d_in[2];
    float*       out    = (float*)d_out;

    softram_packtok_kernel<<<16, 128>>>(tokens);
    softram_main_kernel<<<HH * BB * 2, 128>>>(conn, ram, out);
}